// round 3
// baseline (speedup 1.0000x reference)
#include <cuda_runtime.h>
#include <math.h>

#define Nn 1024
#define Vv 3889
#define NJj 33
#define NBb 41
#define M3 11667   // V*3
#define JRW 3904   // padded row width for transposed J_regressor

// ---------------- scratch (static device allocations) ----------------------
__device__ float g_vshaped[Nn * M3];        // ~48 MB
__device__ float g_A[Nn * 400];             // per-n 33x12 transforms (stride 400)
__device__ float g_SJ[NBb * 99];            // shapedirs folded through J_regressor
__device__ float g_Jt[99];                  // template joints
__device__ float g_jrT[NJj * JRW];          // J_regressor transposed [j][v]

// scal code per (joint, axis): 0 -> 1.0, 1..4 -> exp(betas_logscale[c-1])
__constant__ unsigned char c_sc[99] = {
    0,0,0, 0,0,0, 0,0,0, 0,0,0, 0,0,0, 0,0,0, 0,0,0,
    2,2,1, 2,2,1, 2,2,1, 2,2,1, 2,2,1, 2,2,1, 2,2,1, 2,2,1,
    0,0,0, 0,0,0,
    2,2,1, 2,2,1, 2,2,1, 2,2,1, 2,2,1, 2,2,1, 2,2,1, 2,2,1,
    3,4,4, 3,4,4, 3,4,4, 3,4,4, 3,4,4, 3,4,4, 3,4,4,
    0,0,0
};

// ---------------- packed f32x2 helpers -------------------------------------
typedef unsigned long long u64;
__device__ __forceinline__ u64 pk2(float a, float b) {
    u64 r; asm("mov.b64 %0,{%1,%2};" : "=l"(r) : "f"(a), "f"(b)); return r;
}
__device__ __forceinline__ void upk2(u64 v, float& a, float& b) {
    asm("mov.b64 {%0,%1},%2;" : "=f"(a), "=f"(b) : "l"(v));
}
__device__ __forceinline__ u64 fma2(u64 a, u64 b, u64 c) {
    u64 r; asm("fma.rn.f32x2 %0,%1,%2,%3;" : "=l"(r) : "l"(a), "l"(b), "l"(c)); return r;
}
__device__ __forceinline__ u64 add2(u64 a, u64 b) {
    u64 r; asm("add.rn.f32x2 %0,%1,%2;" : "=l"(r) : "l"(a), "l"(b)); return r;
}

// ---------------- K0: transpose J_regressor --------------------------------
__global__ void k_jrT(const float* __restrict__ jr) {
    int j = blockIdx.y;
    int v = blockIdx.x * 256 + threadIdx.x;
    if (v < Vv) g_jrT[j * JRW + v] = jr[v * NJj + j];
}

// ---------------- K1: fold shapedirs / v_template through J_regressor ------
// block per source row k (42 blocks: 41 shapedirs rows + v_template)
__global__ void __launch_bounds__(128) k_sj(const float* __restrict__ sd,
                                            const float* __restrict__ vt) {
    __shared__ __align__(16) float jrTs[NJj * 258];
    __shared__ __align__(16) float srcT[3 * 264];
    int k = blockIdx.x;
    int tx = threadIdx.x;
    const float* src = (k < NBb) ? (sd + k * M3) : vt;
    u64 acc = 0ull;
    int t = tx, j = tx / 3, a = tx - (tx / 3) * 3;
    for (int chunk = 0; chunk < 16; chunk++) {
        int v0 = chunk * 256;
        int cnt = min(256, Vv - v0);
        for (int i = tx; i < NJj * 256; i += 128) {
            int jj = i >> 8, v = i & 255;
            jrTs[jj * 258 + v] = (v < cnt) ? g_jrT[jj * JRW + v0 + v] : 0.f;
        }
        for (int i = tx; i < 768; i += 128) {
            int v = i / 3, aa = i - v * 3;
            srcT[aa * 264 + v] = (v < cnt) ? src[v0 * 3 + i] : 0.f;
        }
        __syncthreads();
        if (t < 99) {
            const u64* vp = (const u64*)(srcT + a * 264);
            const u64* jp = (const u64*)(jrTs + j * 258);
            #pragma unroll 8
            for (int h = 0; h < 128; h++) acc = fma2(vp[h], jp[h], acc);
        }
        __syncthreads();
    }
    if (t < 99) {
        float lo, hi; upk2(acc, lo, hi);
        float* dst = (k < NBb) ? (g_SJ + k * 99) : g_Jt;
        dst[t] = lo + hi;
    }
}

// ---------------- K2: v_shaped = v_template + beta @ shapedirs -------------
__global__ void __launch_bounds__(128) k_vshape(const float* __restrict__ beta,
                                                const float* __restrict__ sd,
                                                const float* __restrict__ vt) {
    __shared__ u64 bs2[NBb * 16];
    int n0 = blockIdx.y * 32;
    int tx = threadIdx.x;
    for (int i = tx; i < NBb * 16; i += 128) {
        int k = i >> 4, p = i & 15;
        bs2[i] = pk2(beta[(n0 + 2 * p) * NBb + k], beta[(n0 + 2 * p + 1) * NBb + k]);
    }
    __syncthreads();
    int m0 = blockIdx.x * 256 + tx;
    int m1 = m0 + 128;
    bool g0 = m0 < M3, g1 = m1 < M3;
    float base0 = g0 ? vt[m0] : 0.f;
    float base1 = g1 ? vt[m1] : 0.f;
    u64 acc0[16], acc1[16];
    u64 b0 = pk2(base0, base0), b1 = pk2(base1, base1);
    #pragma unroll
    for (int p = 0; p < 16; p++) { acc0[p] = b0; acc1[p] = b1; }
    #pragma unroll 1
    for (int k = 0; k < NBb; k++) {
        float s0 = g0 ? sd[k * M3 + m0] : 0.f;
        float s1 = g1 ? sd[k * M3 + m1] : 0.f;
        u64 sp0 = pk2(s0, s0), sp1 = pk2(s1, s1);
        #pragma unroll
        for (int p = 0; p < 16; p++) {
            u64 bp = bs2[k * 16 + p];
            acc0[p] = fma2(bp, sp0, acc0[p]);
            acc1[p] = fma2(bp, sp1, acc1[p]);
        }
    }
    #pragma unroll
    for (int p = 0; p < 16; p++) {
        float lo, hi;
        if (g0) {
            upk2(acc0[p], lo, hi);
            g_vshaped[(size_t)(n0 + 2 * p) * M3 + m0] = lo;
            g_vshaped[(size_t)(n0 + 2 * p + 1) * M3 + m0] = hi;
        }
        if (g1) {
            upk2(acc1[p], lo, hi);
            g_vshaped[(size_t)(n0 + 2 * p) * M3 + m1] = lo;
            g_vshaped[(size_t)(n0 + 2 * p + 1) * M3 + m1] = hi;
        }
    }
}

// ---------------- K3: rodrigues + kinematic chain --------------------------
__device__ __forceinline__ void rodrigues(const float* __restrict__ th, float R[9]) {
    float t0 = th[0], t1 = th[1], t2 = th[2];
    float a0 = t0 + 1e-8f, a1 = t1 + 1e-8f, a2 = t2 + 1e-8f;
    float ang = sqrtf(a0 * a0 + a1 * a1 + a2 * a2);
    float inv = 1.f / ang;
    float r0 = t0 * inv, r1 = t1 * inv, r2 = t2 * inv;
    float s, c;
    sincosf(ang, &s, &c);
    float oc = 1.f - c;
    R[0] = c + oc * r0 * r0;       R[1] = oc * r0 * r1 - s * r2;  R[2] = oc * r0 * r2 + s * r1;
    R[3] = oc * r0 * r1 + s * r2;  R[4] = c + oc * r1 * r1;       R[5] = oc * r1 * r2 - s * r0;
    R[6] = oc * r0 * r2 - s * r1;  R[7] = oc * r1 * r2 + s * r0;  R[8] = c + oc * r2 * r2;
}

__global__ void k_chain(const float* __restrict__ beta, const float* __restrict__ theta,
                        const float* __restrict__ bls) {
    int n = blockIdx.x * 32 + threadIdx.x;
    if (n >= Nn) return;
    float b[NBb];
    #pragma unroll
    for (int k = 0; k < NBb; k++) b[k] = beta[n * NBb + k];
    float e[5];
    e[0] = 1.f;
    e[1] = expf(bls[n * 6 + 0]);
    e[2] = expf(bls[n * 6 + 1]);
    e[3] = expf(bls[n * 6 + 2]);
    e[4] = expf(bls[n * 6 + 3]);
    const float* th = theta + n * 105;
    float* Aout = g_A + n * 400;

    float Rp[9], tp[3], Jp[3], sp0, sp1, sp2;
    {
        float J0[3] = {g_Jt[0], g_Jt[1], g_Jt[2]};
        #pragma unroll
        for (int k = 0; k < NBb; k++) {
            const float* s = g_SJ + k * 99;
            J0[0] = fmaf(b[k], s[0], J0[0]);
            J0[1] = fmaf(b[k], s[1], J0[1]);
            J0[2] = fmaf(b[k], s[2], J0[2]);
        }
        float R[9];
        rodrigues(th, R);
        #pragma unroll
        for (int r = 0; r < 3; r++) {
            Aout[r * 4 + 0] = R[r * 3 + 0];
            Aout[r * 4 + 1] = R[r * 3 + 1];
            Aout[r * 4 + 2] = R[r * 3 + 2];
            float ib = R[r * 3 + 0] * J0[0] + R[r * 3 + 1] * J0[1] + R[r * 3 + 2] * J0[2];
            Aout[r * 4 + 3] = J0[r] - ib;
        }
        #pragma unroll
        for (int q = 0; q < 9; q++) Rp[q] = R[q];
        tp[0] = J0[0]; tp[1] = J0[1]; tp[2] = J0[2];
        Jp[0] = J0[0]; Jp[1] = J0[1]; Jp[2] = J0[2];
        sp0 = 1.f; sp1 = 1.f; sp2 = 1.f;
    }
    #pragma unroll 1
    for (int i = 1; i < NJj; i++) {
        float Ji[3] = {g_Jt[i * 3 + 0], g_Jt[i * 3 + 1], g_Jt[i * 3 + 2]};
        #pragma unroll
        for (int k = 0; k < NBb; k++) {
            const float* s = g_SJ + k * 99 + i * 3;
            Ji[0] = fmaf(b[k], s[0], Ji[0]);
            Ji[1] = fmaf(b[k], s[1], Ji[1]);
            Ji[2] = fmaf(b[k], s[2], Ji[2]);
        }
        float Ri[9];
        rodrigues(th + i * 3, Ri);
        float s0 = e[c_sc[i * 3 + 0]], s1 = e[c_sc[i * 3 + 1]], s2 = e[c_sc[i * 3 + 2]];
        float ip0 = 1.f / sp0, ip1 = 1.f / sp1, ip2 = 1.f / sp2;
        float Rn[9], tn[3];
        #pragma unroll
        for (int r = 0; r < 3; r++) {
            float m0 = Rp[r * 3 + 0] * ip0;
            float m1 = Rp[r * 3 + 1] * ip1;
            float m2 = Rp[r * 3 + 2] * ip2;
            Rn[r * 3 + 0] = (m0 * Ri[0] + m1 * Ri[3] + m2 * Ri[6]) * s0;
            Rn[r * 3 + 1] = (m0 * Ri[1] + m1 * Ri[4] + m2 * Ri[7]) * s1;
            Rn[r * 3 + 2] = (m0 * Ri[2] + m1 * Ri[5] + m2 * Ri[8]) * s2;
        }
        float d0 = Ji[0] - Jp[0], d1 = Ji[1] - Jp[1], d2 = Ji[2] - Jp[2];
        #pragma unroll
        for (int r = 0; r < 3; r++)
            tn[r] = Rp[r * 3 + 0] * d0 + Rp[r * 3 + 1] * d1 + Rp[r * 3 + 2] * d2 + tp[r];
        float* Ao = Aout + i * 12;
        #pragma unroll
        for (int r = 0; r < 3; r++) {
            Ao[r * 4 + 0] = Rn[r * 3 + 0];
            Ao[r * 4 + 1] = Rn[r * 3 + 1];
            Ao[r * 4 + 2] = Rn[r * 3 + 2];
            float ib = Rn[r * 3 + 0] * Ji[0] + Rn[r * 3 + 1] * Ji[1] + Rn[r * 3 + 2] * Ji[2];
            Ao[r * 4 + 3] = tn[r] - ib;
        }
        #pragma unroll
        for (int q = 0; q < 9; q++) Rp[q] = Rn[q];
        tp[0] = tn[0]; tp[1] = tn[1]; tp[2] = tn[2];
        Jp[0] = Ji[0]; Jp[1] = Ji[1]; Jp[2] = Ji[2];
        sp0 = s0; sp1 = s1; sp2 = s2;
    }
}

// ---------------- K4: skinning, G=4 bodies per block -----------------------
__device__ __forceinline__ int eidx(int v) {
    if (v == 1863) return 0;
    if (v == 26)   return 1;
    if (v == 2124) return 2;
    if (v == 150)  return 3;
    if (v == 3055) return 4;
    if (v == 1097) return 5;
    return -1;
}

__global__ void __launch_bounds__(128) k_skin(const float* __restrict__ wts,
                                              const float* __restrict__ trans,
                                              float* __restrict__ outv,
                                              float* __restrict__ outj) {
    __shared__ __align__(16) float sw[256 * 33];   // weights chunk
    __shared__ __align__(16) u64 As2[2 * 396];     // A interleaved per body-pair
    int chunk = blockIdx.x, n0 = blockIdx.y * 4;
    int v0 = chunk * 256;
    int tx = threadIdx.x;
    int cnt = min(256, Vv - v0);
    int wtot = cnt * 33;
    for (int i = tx; i < 8448; i += 128) sw[i] = (i < wtot) ? wts[v0 * 33 + i] : 0.f;
    for (int i = tx; i < 792; i += 128) {
        int p = i / 396, rc = i - p * 396;
        As2[i] = pk2(g_A[(n0 + 2 * p) * 400 + rc], g_A[(n0 + 2 * p + 1) * 400 + rc]);
    }
    __syncthreads();
    int va = v0 + tx, vb = va + 128;
    bool ga = tx < cnt, gb = tx + 128 < cnt;
    int ea = eidx(va), eb = eidx(vb);

    #pragma unroll 1
    for (int p = 0; p < 2; p++) {
        int b0 = n0 + 2 * p, b1 = b0 + 1;
        u64 vax = 0, vay = 0, vaz = 0, vbx = 0, vby = 0, vbz = 0;
        if (ga) {
            const float* q0 = g_vshaped + (size_t)b0 * M3 + va * 3;
            const float* q1 = g_vshaped + (size_t)b1 * M3 + va * 3;
            vax = pk2(q0[0], q1[0]); vay = pk2(q0[1], q1[1]); vaz = pk2(q0[2], q1[2]);
        }
        if (gb) {
            const float* q0 = g_vshaped + (size_t)b0 * M3 + vb * 3;
            const float* q1 = g_vshaped + (size_t)b1 * M3 + vb * 3;
            vbx = pk2(q0[0], q1[0]); vby = pk2(q0[1], q1[1]); vbz = pk2(q0[2], q1[2]);
        }
        u64 accA[12], accB[12];
        #pragma unroll
        for (int q = 0; q < 12; q++) { accA[q] = 0ull; accB[q] = 0ull; }
        const ulonglong2* Ap = (const ulonglong2*)(As2 + p * 396);
        #pragma unroll 3
        for (int j = 0; j < 33; j++) {
            float wa = sw[tx * 33 + j];
            float wb = sw[(tx + 128) * 33 + j];
            u64 wa2 = pk2(wa, wa), wb2 = pk2(wb, wb);
            #pragma unroll
            for (int r = 0; r < 3; r++) {
                ulonglong2 e0 = Ap[j * 6 + r * 2 + 0];
                ulonglong2 e1 = Ap[j * 6 + r * 2 + 1];
                accA[r * 4 + 0] = fma2(wa2, e0.x, accA[r * 4 + 0]);
                accA[r * 4 + 1] = fma2(wa2, e0.y, accA[r * 4 + 1]);
                accA[r * 4 + 2] = fma2(wa2, e1.x, accA[r * 4 + 2]);
                accA[r * 4 + 3] = fma2(wa2, e1.y, accA[r * 4 + 3]);
                accB[r * 4 + 0] = fma2(wb2, e0.x, accB[r * 4 + 0]);
                accB[r * 4 + 1] = fma2(wb2, e0.y, accB[r * 4 + 1]);
                accB[r * 4 + 2] = fma2(wb2, e1.x, accB[r * 4 + 2]);
                accB[r * 4 + 3] = fma2(wb2, e1.y, accB[r * 4 + 3]);
            }
        }
        u64 tr2[3];
        #pragma unroll
        for (int r = 0; r < 3; r++) tr2[r] = pk2(trans[b0 * 3 + r], trans[b1 * 3 + r]);
        #pragma unroll
        for (int r = 0; r < 3; r++) {
            u64 oA = fma2(accA[r * 4 + 0], vax,
                     fma2(accA[r * 4 + 1], vay,
                     fma2(accA[r * 4 + 2], vaz, add2(accA[r * 4 + 3], tr2[r]))));
            u64 oB = fma2(accB[r * 4 + 0], vbx,
                     fma2(accB[r * 4 + 1], vby,
                     fma2(accB[r * 4 + 2], vbz, add2(accB[r * 4 + 3], tr2[r]))));
            float lo, hi;
            if (ga) {
                upk2(oA, lo, hi);
                outv[(size_t)b0 * M3 + va * 3 + r] = lo;
                outv[(size_t)b1 * M3 + va * 3 + r] = hi;
                if (ea >= 0) {
                    outj[b0 * 117 + (33 + ea) * 3 + r] = lo;
                    outj[b1 * 117 + (33 + ea) * 3 + r] = hi;
                }
            }
            if (gb) {
                upk2(oB, lo, hi);
                outv[(size_t)b0 * M3 + vb * 3 + r] = lo;
                outv[(size_t)b1 * M3 + vb * 3 + r] = hi;
                if (eb >= 0) {
                    outj[b0 * 117 + (33 + eb) * 3 + r] = lo;
                    outj[b1 * 117 + (33 + eb) * 3 + r] = hi;
                }
            }
        }
    }
}

// ---------------- K5: joints = Jr^T @ verts, G=2 bodies per block ----------
__global__ void __launch_bounds__(256) k_joints(const float* __restrict__ verts,
                                                float* __restrict__ outj) {
    __shared__ __align__(16) float jrTs[NJj * 258];  // 34056 B
    __shared__ __align__(16) float vsT[2 * 3 * 264]; // 6336 B
    int n0 = blockIdx.x * 2;
    int tx = threadIdx.x;
    int g = tx / 99, q2 = tx - g * 99;
    int j = q2 / 3, a = q2 - j * 3;
    bool act = tx < 198;
    u64 acc0 = 0ull, acc1 = 0ull;
    for (int chunk = 0; chunk < 16; chunk++) {
        int v0 = chunk * 256;
        int cnt = min(256, Vv - v0);
        for (int i = tx; i < NJj * 256; i += 256) {
            int jj = i >> 8, v = i & 255;
            jrTs[jj * 258 + v] = (v < cnt) ? g_jrT[jj * JRW + v0 + v] : 0.f;
        }
        for (int i = tx; i < 1536; i += 256) {
            int b = i / 768, q = i - b * 768;
            int v = q / 3, aa = q - v * 3;
            vsT[(b * 3 + aa) * 264 + v] =
                (v < cnt) ? verts[(size_t)(n0 + b) * M3 + v0 * 3 + q] : 0.f;
        }
        __syncthreads();
        if (act) {
            const u64* jp = (const u64*)(jrTs + j * 258) + g * 64;
            const u64* p0 = (const u64*)(vsT + a * 264) + g * 64;
            const u64* p1 = (const u64*)(vsT + (3 + a) * 264) + g * 64;
            #pragma unroll 8
            for (int h = 0; h < 64; h++) {
                u64 jv = jp[h];
                acc0 = fma2(p0[h], jv, acc0);
                acc1 = fma2(p1[h], jv, acc1);
            }
        }
        __syncthreads();
    }
    // slice reduce via smem (reuse vsT)
    float* sr = vsT;
    if (act) {
        float lo, hi;
        upk2(acc0, lo, hi); sr[tx * 2 + 0] = lo + hi;
        upk2(acc1, lo, hi); sr[tx * 2 + 1] = lo + hi;
    }
    __syncthreads();
    if (tx < 198) {
        int b = tx / 99, q = tx - b * 99;
        outj[(n0 + b) * 117 + q] = sr[q * 2 + b] + sr[(99 + q) * 2 + b];
    }
}

// ---------------- launch ---------------------------------------------------
extern "C" void kernel_launch(void* const* d_in, const int* in_sizes, int n_in,
                              void* d_out, int out_size) {
    const float* beta  = (const float*)d_in[0];
    const float* theta = (const float*)d_in[1];
    const float* trans = (const float*)d_in[2];
    const float* bls   = (const float*)d_in[3];
    const float* sd    = (const float*)d_in[4];
    const float* vt    = (const float*)d_in[5];
    const float* jreg  = (const float*)d_in[6];
    // d_in[7] = posedirs: multiplied by exact zeros in the reference -> unused
    const float* wts   = (const float*)d_in[8];
    float* outv = (float*)d_out;
    float* outj = outv + (size_t)Nn * M3;

    k_jrT   <<<dim3(16, 33), 256>>>(jreg);
    k_sj    <<<42, 128>>>(sd, vt);
    k_vshape<<<dim3(46, 32), 128>>>(beta, sd, vt);
    k_chain <<<32, 32>>>(beta, theta, bls);
    k_skin  <<<dim3(16, 256), 128>>>(wts, trans, outv, outj);
    k_joints<<<512, 256>>>(outv, outj);
}

// round 4
// speedup vs baseline: 1.4312x; 1.4312x over previous
#include <cuda_runtime.h>
#include <math.h>

#define Nn 1024
#define Vv 3889
#define NJj 33
#define NBb 41
#define M3 11667   // V*3
#define JRW 3904   // padded row width for transposed J_regressor

// ---------------- scratch (static device allocations) ----------------------
__device__ float g_vshaped[Nn * M3];          // ~48 MB
__device__ float g_L[Nn * 400];               // per-(n,i) local transforms
__device__ float g_J[Nn * 99];                // per-(n,i) joint positions
__device__ __align__(16) float g_A2f[512 * 396 * 2]; // A packed per body-pair (f32x2 lanes)
__device__ float g_SJ[NBb * 99];              // shapedirs folded through J_regressor
__device__ float g_Jt[99];                    // template joints
__device__ float g_jrT[NJj * JRW];            // J_regressor transposed [j][v]
__device__ float g_jpart[Nn * 16 * 99];       // per-chunk joint partials

// scal code per (joint, axis): 0 -> 1.0, 1..4 -> exp(betas_logscale[c-1])
__constant__ unsigned char c_sc[99] = {
    0,0,0, 0,0,0, 0,0,0, 0,0,0, 0,0,0, 0,0,0, 0,0,0,
    2,2,1, 2,2,1, 2,2,1, 2,2,1, 2,2,1, 2,2,1, 2,2,1, 2,2,1,
    0,0,0, 0,0,0,
    2,2,1, 2,2,1, 2,2,1, 2,2,1, 2,2,1, 2,2,1, 2,2,1, 2,2,1,
    3,4,4, 3,4,4, 3,4,4, 3,4,4, 3,4,4, 3,4,4, 3,4,4,
    0,0,0
};

// ---------------- packed f32x2 helpers -------------------------------------
typedef unsigned long long u64;
__device__ __forceinline__ u64 pk2(float a, float b) {
    u64 r; asm("mov.b64 %0,{%1,%2};" : "=l"(r) : "f"(a), "f"(b)); return r;
}
__device__ __forceinline__ void upk2(u64 v, float& a, float& b) {
    asm("mov.b64 {%0,%1},%2;" : "=f"(a), "=f"(b) : "l"(v));
}
__device__ __forceinline__ u64 fma2(u64 a, u64 b, u64 c) {
    u64 r; asm("fma.rn.f32x2 %0,%1,%2,%3;" : "=l"(r) : "l"(a), "l"(b), "l"(c)); return r;
}
__device__ __forceinline__ u64 add2(u64 a, u64 b) {
    u64 r; asm("add.rn.f32x2 %0,%1,%2;" : "=l"(r) : "l"(a), "l"(b)); return r;
}

// ---------------- K0: transpose J_regressor --------------------------------
__global__ void k_jrT(const float* __restrict__ jr) {
    int j = blockIdx.y;
    int v = blockIdx.x * 256 + threadIdx.x;
    if (v < Vv) g_jrT[j * JRW + v] = jr[v * NJj + j];
}

// ---------------- K1: fold shapedirs / v_template through J_regressor ------
// grid (42, 33): block per (source row k, joint j); coalesced jrT reads.
__global__ void __launch_bounds__(256) k_sj(const float* __restrict__ sd,
                                            const float* __restrict__ vt) {
    int k = blockIdx.x, j = blockIdx.y;
    const float* src = (k < NBb) ? (sd + k * M3) : vt;
    const float* jrow = g_jrT + j * JRW;
    float a0 = 0.f, a1 = 0.f, a2 = 0.f;
    for (int v = threadIdx.x; v < Vv; v += 256) {
        float w = jrow[v];
        a0 = fmaf(w, src[v * 3 + 0], a0);
        a1 = fmaf(w, src[v * 3 + 1], a1);
        a2 = fmaf(w, src[v * 3 + 2], a2);
    }
    #pragma unroll
    for (int off = 16; off; off >>= 1) {
        a0 += __shfl_down_sync(0xffffffffu, a0, off);
        a1 += __shfl_down_sync(0xffffffffu, a1, off);
        a2 += __shfl_down_sync(0xffffffffu, a2, off);
    }
    __shared__ float r0[8], r1[8], r2[8];
    int wid = threadIdx.x >> 5, lane = threadIdx.x & 31;
    if (lane == 0) { r0[wid] = a0; r1[wid] = a1; r2[wid] = a2; }
    __syncthreads();
    if (threadIdx.x == 0) {
        a0 = a1 = a2 = 0.f;
        #pragma unroll
        for (int w = 0; w < 8; w++) { a0 += r0[w]; a1 += r1[w]; a2 += r2[w]; }
        float* dst = (k < NBb) ? (g_SJ + k * 99 + j * 3) : (g_Jt + j * 3);
        dst[0] = a0; dst[1] = a1; dst[2] = a2;
    }
}

// ---------------- K2: v_shaped = v_template + beta @ shapedirs -------------
__global__ void __launch_bounds__(128) k_vshape(const float* __restrict__ beta,
                                                const float* __restrict__ sd,
                                                const float* __restrict__ vt) {
    __shared__ u64 bs2[NBb * 16];
    int n0 = blockIdx.y * 32;
    int tx = threadIdx.x;
    for (int i = tx; i < NBb * 16; i += 128) {
        int k = i >> 4, p = i & 15;
        bs2[i] = pk2(beta[(n0 + 2 * p) * NBb + k], beta[(n0 + 2 * p + 1) * NBb + k]);
    }
    __syncthreads();
    int m0 = blockIdx.x * 256 + tx;
    int m1 = m0 + 128;
    bool g0 = m0 < M3, g1 = m1 < M3;
    float base0 = g0 ? vt[m0] : 0.f;
    float base1 = g1 ? vt[m1] : 0.f;
    u64 acc0[16], acc1[16];
    u64 b0 = pk2(base0, base0), b1 = pk2(base1, base1);
    #pragma unroll
    for (int p = 0; p < 16; p++) { acc0[p] = b0; acc1[p] = b1; }
    #pragma unroll 1
    for (int k = 0; k < NBb; k++) {
        float s0 = g0 ? sd[k * M3 + m0] : 0.f;
        float s1 = g1 ? sd[k * M3 + m1] : 0.f;
        u64 sp0 = pk2(s0, s0), sp1 = pk2(s1, s1);
        #pragma unroll
        for (int p = 0; p < 16; p++) {
            u64 bp = bs2[k * 16 + p];
            acc0[p] = fma2(bp, sp0, acc0[p]);
            acc1[p] = fma2(bp, sp1, acc1[p]);
        }
    }
    #pragma unroll
    for (int p = 0; p < 16; p++) {
        float lo, hi;
        if (g0) {
            upk2(acc0[p], lo, hi);
            g_vshaped[(size_t)(n0 + 2 * p) * M3 + m0] = lo;
            g_vshaped[(size_t)(n0 + 2 * p + 1) * M3 + m0] = hi;
        }
        if (g1) {
            upk2(acc1[p], lo, hi);
            g_vshaped[(size_t)(n0 + 2 * p) * M3 + m1] = lo;
            g_vshaped[(size_t)(n0 + 2 * p + 1) * M3 + m1] = hi;
        }
    }
}

// ---------------- K3a: per-(n,i) local transforms (fully parallel) ---------
__device__ __forceinline__ void rodrigues(const float* __restrict__ th, float R[9]) {
    float t0 = th[0], t1 = th[1], t2 = th[2];
    float a0 = t0 + 1e-8f, a1 = t1 + 1e-8f, a2 = t2 + 1e-8f;
    float ang = sqrtf(a0 * a0 + a1 * a1 + a2 * a2);
    float inv = 1.f / ang;
    float r0 = t0 * inv, r1 = t1 * inv, r2 = t2 * inv;
    float s, c;
    sincosf(ang, &s, &c);
    float oc = 1.f - c;
    R[0] = c + oc * r0 * r0;       R[1] = oc * r0 * r1 - s * r2;  R[2] = oc * r0 * r2 + s * r1;
    R[3] = oc * r0 * r1 + s * r2;  R[4] = c + oc * r1 * r1;       R[5] = oc * r1 * r2 - s * r0;
    R[6] = oc * r0 * r2 - s * r1;  R[7] = oc * r1 * r2 + s * r0;  R[8] = c + oc * r2 * r2;
}

__global__ void __launch_bounds__(256) k_local(const float* __restrict__ beta,
                                               const float* __restrict__ theta,
                                               const float* __restrict__ bls) {
    int id = blockIdx.x * 256 + threadIdx.x;
    if (id >= Nn * NJj) return;
    int n = id / NJj, i = id - n * NJj;
    const float* b = beta + n * NBb;
    float e[5];
    e[0] = 1.f;
    e[1] = expf(bls[n * 6 + 0]);
    e[2] = expf(bls[n * 6 + 1]);
    e[3] = expf(bls[n * 6 + 2]);
    e[4] = expf(bls[n * 6 + 3]);

    float Ji[3] = {g_Jt[i * 3 + 0], g_Jt[i * 3 + 1], g_Jt[i * 3 + 2]};
    #pragma unroll
    for (int k = 0; k < NBb; k++) {
        const float* s = g_SJ + k * 99 + i * 3;
        float bk = b[k];
        Ji[0] = fmaf(bk, s[0], Ji[0]);
        Ji[1] = fmaf(bk, s[1], Ji[1]);
        Ji[2] = fmaf(bk, s[2], Ji[2]);
    }
    g_J[n * 99 + i * 3 + 0] = Ji[0];
    g_J[n * 99 + i * 3 + 1] = Ji[1];
    g_J[n * 99 + i * 3 + 2] = Ji[2];

    float R[9];
    rodrigues(theta + n * 105 + i * 3, R);
    float* L = g_L + n * 400 + i * 12;
    if (i == 0) {
        #pragma unroll
        for (int r = 0; r < 3; r++) {
            L[r * 4 + 0] = R[r * 3 + 0];
            L[r * 4 + 1] = R[r * 3 + 1];
            L[r * 4 + 2] = R[r * 3 + 2];
            L[r * 4 + 3] = Ji[r];
        }
    } else {
        int p = i - 1;
        float Jp[3] = {g_Jt[p * 3 + 0], g_Jt[p * 3 + 1], g_Jt[p * 3 + 2]};
        #pragma unroll
        for (int k = 0; k < NBb; k++) {
            const float* s = g_SJ + k * 99 + p * 3;
            float bk = b[k];
            Jp[0] = fmaf(bk, s[0], Jp[0]);
            Jp[1] = fmaf(bk, s[1], Jp[1]);
            Jp[2] = fmaf(bk, s[2], Jp[2]);
        }
        float si0 = e[c_sc[i * 3 + 0]], si1 = e[c_sc[i * 3 + 1]], si2 = e[c_sc[i * 3 + 2]];
        float sp0 = e[c_sc[p * 3 + 0]], sp1 = e[c_sc[p * 3 + 1]], sp2 = e[c_sc[p * 3 + 2]];
        float ipr[3] = {1.f / sp0, 1.f / sp1, 1.f / sp2};
        float sic[3] = {si0, si1, si2};
        #pragma unroll
        for (int r = 0; r < 3; r++) {
            #pragma unroll
            for (int c = 0; c < 3; c++)
                L[r * 4 + c] = R[r * 3 + c] * sic[c] * ipr[r];
            L[r * 4 + 3] = Ji[r] - Jp[r];
        }
    }
}

// ---------------- K3b: sequential compose (1024 threads, tiny) -------------
__global__ void __launch_bounds__(128) k_compose() {
    int n = blockIdx.x * 128 + threadIdx.x;
    if (n >= Nn) return;
    const float* Lbase = g_L + n * 400;
    const float* Jbase = g_J + n * 99;
    int pr = n >> 1, lane = n & 1;
    float* out = g_A2f + ((size_t)pr * 396) * 2 + lane;
    float G[12];
    #pragma unroll
    for (int q = 0; q < 12; q++) G[q] = Lbase[q];
    #pragma unroll 1
    for (int i = 0; i < NJj; i++) {
        if (i > 0) {
            const float* L = Lbase + i * 12;
            float Gn[12];
            #pragma unroll
            for (int r = 0; r < 3; r++) {
                #pragma unroll
                for (int c = 0; c < 4; c++) {
                    float acc = (c == 3) ? G[r * 4 + 3] : 0.f;
                    acc = fmaf(G[r * 4 + 0], L[0 * 4 + c], acc);
                    acc = fmaf(G[r * 4 + 1], L[1 * 4 + c], acc);
                    acc = fmaf(G[r * 4 + 2], L[2 * 4 + c], acc);
                    Gn[r * 4 + c] = acc;
                }
            }
            #pragma unroll
            for (int q = 0; q < 12; q++) G[q] = Gn[q];
        }
        float jx = Jbase[i * 3 + 0], jy = Jbase[i * 3 + 1], jz = Jbase[i * 3 + 2];
        #pragma unroll
        for (int r = 0; r < 3; r++) {
            float ib = G[r * 4 + 0] * jx + G[r * 4 + 1] * jy + G[r * 4 + 2] * jz;
            out[(i * 12 + r * 4 + 0) * 2] = G[r * 4 + 0];
            out[(i * 12 + r * 4 + 1) * 2] = G[r * 4 + 1];
            out[(i * 12 + r * 4 + 2) * 2] = G[r * 4 + 2];
            out[(i * 12 + r * 4 + 3) * 2] = G[r * 4 + 3] - ib;
        }
    }
}

// ---------------- K4: skinning; block = (chunk, 32-body group) -------------
__device__ __forceinline__ int eidx(int v) {
    if (v == 1863) return 0;
    if (v == 26)   return 1;
    if (v == 2124) return 2;
    if (v == 150)  return 3;
    if (v == 3055) return 4;
    if (v == 1097) return 5;
    return -1;
}

__global__ void __launch_bounds__(128) k_skin(const float* __restrict__ wts,
                                              const float* __restrict__ trans,
                                              float* __restrict__ outv,
                                              float* __restrict__ outj) {
    __shared__ __align__(16) float sw[256 * 33];   // weights chunk (staged once)
    __shared__ __align__(16) u64 As2[396];         // A for current body-pair
    int chunk = blockIdx.x, n0 = blockIdx.y * 32;
    int v0 = chunk * 256;
    int tx = threadIdx.x;
    int cnt = min(256, Vv - v0);
    int wtot = cnt * 33;
    for (int i = tx; i < 8448; i += 128) sw[i] = (i < wtot) ? wts[v0 * 33 + i] : 0.f;
    int va = v0 + tx, vb = va + 128;
    bool ga = tx < cnt, gb = tx + 128 < cnt;
    int ea = eidx(va), eb = eidx(vb);
    const u64* gA2 = (const u64*)g_A2f;

    #pragma unroll 1
    for (int pair = 0; pair < 16; pair++) {
        int pr = (n0 >> 1) + pair;
        int b0 = 2 * pr, b1 = b0 + 1;
        __syncthreads();
        for (int i = tx; i < 396; i += 128) As2[i] = gA2[(size_t)pr * 396 + i];
        __syncthreads();

        u64 vax = 0, vay = 0, vaz = 0, vbx = 0, vby = 0, vbz = 0;
        if (ga) {
            const float* q0 = g_vshaped + (size_t)b0 * M3 + va * 3;
            const float* q1 = g_vshaped + (size_t)b1 * M3 + va * 3;
            vax = pk2(q0[0], q1[0]); vay = pk2(q0[1], q1[1]); vaz = pk2(q0[2], q1[2]);
        }
        if (gb) {
            const float* q0 = g_vshaped + (size_t)b0 * M3 + vb * 3;
            const float* q1 = g_vshaped + (size_t)b1 * M3 + vb * 3;
            vbx = pk2(q0[0], q1[0]); vby = pk2(q0[1], q1[1]); vbz = pk2(q0[2], q1[2]);
        }
        u64 accA[12], accB[12];
        #pragma unroll
        for (int q = 0; q < 12; q++) { accA[q] = 0ull; accB[q] = 0ull; }
        const ulonglong2* Ap = (const ulonglong2*)As2;
        #pragma unroll 3
        for (int j = 0; j < 33; j++) {
            float wa = sw[tx * 33 + j];
            float wb = sw[(tx + 128) * 33 + j];
            u64 wa2 = pk2(wa, wa), wb2 = pk2(wb, wb);
            #pragma unroll
            for (int r = 0; r < 3; r++) {
                ulonglong2 e0 = Ap[j * 6 + r * 2 + 0];
                ulonglong2 e1 = Ap[j * 6 + r * 2 + 1];
                accA[r * 4 + 0] = fma2(wa2, e0.x, accA[r * 4 + 0]);
                accA[r * 4 + 1] = fma2(wa2, e0.y, accA[r * 4 + 1]);
                accA[r * 4 + 2] = fma2(wa2, e1.x, accA[r * 4 + 2]);
                accA[r * 4 + 3] = fma2(wa2, e1.y, accA[r * 4 + 3]);
                accB[r * 4 + 0] = fma2(wb2, e0.x, accB[r * 4 + 0]);
                accB[r * 4 + 1] = fma2(wb2, e0.y, accB[r * 4 + 1]);
                accB[r * 4 + 2] = fma2(wb2, e1.x, accB[r * 4 + 2]);
                accB[r * 4 + 3] = fma2(wb2, e1.y, accB[r * 4 + 3]);
            }
        }
        u64 tr2[3];
        #pragma unroll
        for (int r = 0; r < 3; r++) tr2[r] = pk2(trans[b0 * 3 + r], trans[b1 * 3 + r]);
        #pragma unroll
        for (int r = 0; r < 3; r++) {
            u64 oA = fma2(accA[r * 4 + 0], vax,
                     fma2(accA[r * 4 + 1], vay,
                     fma2(accA[r * 4 + 2], vaz, add2(accA[r * 4 + 3], tr2[r]))));
            u64 oB = fma2(accB[r * 4 + 0], vbx,
                     fma2(accB[r * 4 + 1], vby,
                     fma2(accB[r * 4 + 2], vbz, add2(accB[r * 4 + 3], tr2[r]))));
            float lo, hi;
            if (ga) {
                upk2(oA, lo, hi);
                outv[(size_t)b0 * M3 + va * 3 + r] = lo;
                outv[(size_t)b1 * M3 + va * 3 + r] = hi;
                if (ea >= 0) {
                    outj[b0 * 117 + (33 + ea) * 3 + r] = lo;
                    outj[b1 * 117 + (33 + ea) * 3 + r] = hi;
                }
            }
            if (gb) {
                upk2(oB, lo, hi);
                outv[(size_t)b0 * M3 + vb * 3 + r] = lo;
                outv[(size_t)b1 * M3 + vb * 3 + r] = hi;
                if (eb >= 0) {
                    outj[b0 * 117 + (33 + eb) * 3 + r] = lo;
                    outj[b1 * 117 + (33 + eb) * 3 + r] = hi;
                }
            }
        }
    }
}

// ---------------- K5: joint partials; block = (chunk, 32-body group) -------
__global__ void __launch_bounds__(256) k_joints(const float* __restrict__ verts) {
    __shared__ __align__(16) float jrTs[NJj * 258];  // chunk of jrT (staged once)
    __shared__ __align__(16) float vsT[6 * 264];     // verts of current pair, transposed
    __shared__ float red[396];
    int chunk = blockIdx.x, n0 = blockIdx.y * 32;
    int v0 = chunk * 256;
    int tx = threadIdx.x;
    int cnt = min(256, Vv - v0);
    for (int i = tx; i < NJj * 256; i += 256) {
        int jj = i >> 8, v = i & 255;
        jrTs[jj * 258 + v] = (v < cnt) ? g_jrT[jj * JRW + v0 + v] : 0.f;
    }
    int g = tx / 99, q2 = tx - g * 99;
    int j = q2 / 3, a = q2 - j * 3;
    bool act = tx < 198;

    #pragma unroll 1
    for (int pair = 0; pair < 16; pair++) {
        int b0 = n0 + 2 * pair, b1 = b0 + 1;
        __syncthreads();  // protects vsT & red reuse
        for (int i = tx; i < 1536; i += 256) {
            int b = i / 768, q = i - b * 768;
            int v = q / 3, aa = q - v * 3;
            vsT[(b * 3 + aa) * 264 + v] =
                (v < cnt) ? verts[(size_t)(b0 + b) * M3 + v0 * 3 + q] : 0.f;
        }
        __syncthreads();
        u64 acc0 = 0ull, acc1 = 0ull;
        if (act) {
            const u64* jp = (const u64*)(jrTs + j * 258) + g * 64;
            const u64* p0 = (const u64*)(vsT + a * 264) + g * 64;
            const u64* p1 = (const u64*)(vsT + (3 + a) * 264) + g * 64;
            #pragma unroll 8
            for (int h = 0; h < 64; h++) {
                u64 jv = jp[h];
                acc0 = fma2(p0[h], jv, acc0);
                acc1 = fma2(p1[h], jv, acc1);
            }
            float lo, hi;
            upk2(acc0, lo, hi); red[(g * 99 + q2) * 2 + 0] = lo + hi;
            upk2(acc1, lo, hi); red[(g * 99 + q2) * 2 + 1] = lo + hi;
        }
        __syncthreads();
        if (tx < 198) {
            int b = tx / 99, q = tx - b * 99;
            float s = red[q * 2 + b] + red[(99 + q) * 2 + b];
            g_jpart[((size_t)(b0 + b) * 16 + chunk) * 99 + q] = s;
        }
    }
}

// ---------------- K6: deterministic joint reduce ---------------------------
__global__ void k_jred(float* __restrict__ outj) {
    int idx = blockIdx.x * 256 + threadIdx.x;
    if (idx >= Nn * 99) return;
    int n = idx / 99, t = idx - n * 99;
    const float* p = g_jpart + (size_t)n * 16 * 99 + t;
    float acc = 0.f;
    #pragma unroll
    for (int c = 0; c < 16; c++) acc += p[c * 99];
    outj[n * 117 + t] = acc;
}

// ---------------- launch ---------------------------------------------------
extern "C" void kernel_launch(void* const* d_in, const int* in_sizes, int n_in,
                              void* d_out, int out_size) {
    const float* beta  = (const float*)d_in[0];
    const float* theta = (const float*)d_in[1];
    const float* trans = (const float*)d_in[2];
    const float* bls   = (const float*)d_in[3];
    const float* sd    = (const float*)d_in[4];
    const float* vt    = (const float*)d_in[5];
    const float* jreg  = (const float*)d_in[6];
    // d_in[7] = posedirs: multiplied by exact zeros in the reference -> unused
    const float* wts   = (const float*)d_in[8];
    float* outv = (float*)d_out;
    float* outj = outv + (size_t)Nn * M3;

    k_jrT    <<<dim3(16, 33), 256>>>(jreg);
    k_sj     <<<dim3(42, 33), 256>>>(sd, vt);
    k_vshape <<<dim3(46, 32), 128>>>(beta, sd, vt);
    k_local  <<<132, 256>>>(beta, theta, bls);
    k_compose<<<8, 128>>>();
    k_skin   <<<dim3(16, 32), 128>>>(wts, trans, outv, outj);
    k_joints <<<dim3(16, 32), 256>>>(outv);
    k_jred   <<<(Nn * 99 + 255) / 256, 256>>>(outj);
}